// round 15
// baseline (speedup 1.0000x reference)
#include <cuda_runtime.h>
#include <math.h>
#include <stdint.h>

#define B_Q    1024
#define NCORP  262144
#define KDIM   256
#define DMODEL 1024
#define TOPK   8
#define NCAND  256
#define PCHUNK 32                    // raw entries per (query, chunk)

#define TM      128
#define TN      128
#define NCHUNKS 128
#define CHUNK   2048
#define NTILES  16
#define QTILES  8
#define NSLABS_TOTAL (NTILES * 2)    // 32 x 128-elem K slabs

// byte pitches (odd 16B-unit counts -> conflict-free ldsm)
#define LDA_B  272      // A s8: 256B data + 16B pad
#define LDB_B  144      // B s8 slab: 128B data + 16B pad

#define SM_A     0
#define A_BYTES  (128 * LDA_B)              // 34816
#define SM_B     A_BYTES
#define SB_BYTES (128 * LDB_B)              // 18432 per buffer
#define SMEM_TOTAL (SM_B + 2 * SB_BYTES)    // 71680

#define QSCALE 256.0f

// ---- device-global scratch ----
__device__ unsigned char g_qs8[B_Q * KDIM];
__device__ float         g_qn[B_Q * KDIM];
__device__ unsigned char g_keysS8[(size_t)NCORP * KDIM];           // 64 MB
__device__ float         g_pscore[(size_t)B_Q * NCHUNKS * PCHUNK]; // 16 MB
__device__ int           g_pidx[(size_t)B_Q * NCHUNKS * PCHUNK];   // 16 MB
__device__ int           g_cand[B_Q * NCAND];                      // 1 MB
__device__ int           g_topidx[B_Q * TOPK];

__device__ __forceinline__ bool better(float s1, int i1, float s2, int i2) {
    return (s1 > s2) || (s1 == s2 && i1 < i2);
}
__device__ __forceinline__ uint32_t smem_u32(const void* p) {
    return (uint32_t)__cvta_generic_to_shared(p);
}
__device__ __forceinline__ void ldsm_x4(unsigned* r, unsigned addr) {
    asm volatile("ldmatrix.sync.aligned.m8n8.x4.shared.b16 {%0,%1,%2,%3}, [%4];\n"
        : "=r"(r[0]), "=r"(r[1]), "=r"(r[2]), "=r"(r[3]) : "r"(addr));
}
// int8 IMMA: m16n8k32 s8*s8 -> s32, fragment bytes identical to fp8 path
__device__ __forceinline__ void mma16832_s8(int* d, const unsigned* a, const unsigned* b) {
    asm volatile(
        "mma.sync.aligned.m16n8k32.row.col.s32.s8.s8.s32 "
        "{%0,%1,%2,%3}, {%4,%5,%6,%7}, {%8,%9}, {%0,%1,%2,%3};\n"
        : "+r"(d[0]), "+r"(d[1]), "+r"(d[2]), "+r"(d[3])
        : "r"(a[0]), "r"(a[1]), "r"(a[2]), "r"(a[3]), "r"(b[0]), "r"(b[1]));
}
#define CP_ASYNC16(dst, src) \
    asm volatile("cp.async.cg.shared.global [%0], [%1], 16;" :: "r"(dst), "l"(src))
#define CP_COMMIT() asm volatile("cp.async.commit_group;" ::: "memory")
#define CP_WAIT1()  asm volatile("cp.async.wait_group 1;" ::: "memory")
#define CP_WAIT0()  asm volatile("cp.async.wait_group 0;" ::: "memory")

__device__ __forceinline__ void ins8(float ts[8], int ti[8], float v, int idx) {
    ts[7] = v; ti[7] = idx;
#pragma unroll
    for (int j = 7; j > 0; j--) {
        if (ts[j] > ts[j - 1]) {
            float tf = ts[j]; ts[j] = ts[j - 1]; ts[j - 1] = tf;
            int   tt = ti[j]; ti[j] = ti[j - 1]; ti[j - 1] = tt;
        }
    }
}

__device__ __forceinline__ signed char to_s8(float v) {
    return (signed char)__float2int_rn(fminf(fmaxf(v * QSCALE, -127.f), 127.f));
}

// ---- kernel 1: normalize queries -> fp32 + s8 ----
__global__ void qnorm_kernel(const float* __restrict__ q) {
    int row  = (blockIdx.x * blockDim.x + threadIdx.x) >> 5;
    int lane = threadIdx.x & 31;
    if (row >= B_Q) return;
    float x[8];
    *(float4*)&x[0] = *(const float4*)(q + row * KDIM + lane * 8);
    *(float4*)&x[4] = *(const float4*)(q + row * KDIM + lane * 8 + 4);
    float ss = 0.f;
#pragma unroll
    for (int e = 0; e < 8; e++) ss += x[e] * x[e];
#pragma unroll
    for (int o = 16; o > 0; o >>= 1) ss += __shfl_xor_sync(0xffffffffu, ss, o);
    float rinv = 1.0f / fmaxf(sqrtf(ss), 1e-12f);
    signed char ob[8];
#pragma unroll
    for (int e = 0; e < 8; e++) {
        float v = x[e] * rinv;
        g_qn[row * KDIM + lane * 8 + e] = v;
        ob[e] = to_s8(v);
    }
    *(uint2*)(g_qs8 + row * KDIM + lane * 8) = *(uint2*)ob;
}

// ---- kernel 2: normalize keys -> s8 row-major ----
__global__ void keysprep_kernel(const float* __restrict__ keys) {
    int row  = (blockIdx.x * blockDim.x + threadIdx.x) >> 5;
    int lane = threadIdx.x & 31;
    if (row >= NCORP) return;
    float x[8];
    *(float4*)&x[0] = *(const float4*)(keys + (size_t)row * KDIM + lane * 8);
    *(float4*)&x[4] = *(const float4*)(keys + (size_t)row * KDIM + lane * 8 + 4);
    float ss = 0.f;
#pragma unroll
    for (int e = 0; e < 8; e++) ss += x[e] * x[e];
#pragma unroll
    for (int o = 16; o > 0; o >>= 1) ss += __shfl_xor_sync(0xffffffffu, ss, o);
    float rinv = 1.0f / fmaxf(sqrtf(ss), 1e-12f);
    signed char ob[8];
#pragma unroll
    for (int e = 0; e < 8; e++) ob[e] = to_s8(x[e] * rinv);
    *(uint2*)(g_keysS8 + (size_t)row * KDIM + lane * 8) = *(uint2*)ob;
}

// ---- kernel 3: int8 IMMA GEMM; fragment-local depth-2 lists; no epilogue smem ----
__global__ __launch_bounds__(512, 1) void score_kernel() {
    extern __shared__ char smem[];
    char* sA = smem + SM_A;
    char* sB = smem + SM_B;

    const int t = threadIdx.x, lane = t & 31, wid = t >> 5;
    const int wm = wid >> 2, wn = wid & 3;          // 4x4 warp grid, 32x32 tiles
    const int q0 = blockIdx.x * TM;
    const int c0 = blockIdx.y * CHUNK;

    // A resident fill: 128 rows x 256B s8
#pragma unroll
    for (int i = 0; i < 4; i++) {
        int u = i * 512 + t; int row = u >> 4, seg = u & 15;
        uint4 v = *(const uint4*)(g_qs8 + (size_t)(q0 + row) * KDIM + seg * 16);
        *(uint4*)(sA + row * LDA_B + seg * 16) = v;
    }

    // ldsm base addresses (byte layout identical to fp8 path)
    unsigned aAddr[2];
    {
        int r = lane & 15, c8 = lane >> 4;
#pragma unroll
        for (int mi = 0; mi < 2; mi++)
            aAddr[mi] = smem_u32(sA + (wm * 32 + mi * 16 + r) * LDA_B + c8 * 16);
    }
    unsigned bAddr[2][2];
    {
        int bn = (lane & 7) + ((lane >> 4) << 3);
        int bk = ((lane >> 3) & 1) * 16;
#pragma unroll
        for (int buf = 0; buf < 2; buf++)
#pragma unroll
            for (int np = 0; np < 2; np++)
                bAddr[buf][np] = smem_u32(sB + buf * SB_BYTES +
                                          (wn * 32 + np * 16 + bn) * LDB_B + bk);
    }

    // fragment-local depth-2 lists: 4 rows per thread (mi x half)
    int lv0[4], lv1[4], li0[4], li1[4];
#pragma unroll
    for (int L = 0; L < 4; L++) {
        lv0[L] = INT32_MIN; lv1[L] = INT32_MIN;
        li0[L] = 0x7fffffff; li1[L] = 0x7fffffff;
    }

    // cp.async: slab gs (tile gs>>1, K-half gs&1) -> buffer buf
    auto issue_B = [&](int gs, int buf) {
        const int nt = gs >> 1, s = gs & 1;
        const unsigned char* src = g_keysS8 + (size_t)(c0 + nt * TN) * KDIM + s * 128;
        char* dst = sB + buf * SB_BYTES;
#pragma unroll
        for (int i = 0; i < 2; i++) {
            int u = i * 512 + t; int row = u >> 3, seg = u & 7;
            CP_ASYNC16(smem_u32(dst + row * LDB_B + seg * 16),
                       (const void*)(src + (size_t)row * KDIM + seg * 16));
        }
    };

    int acc[2][4][4];

    issue_B(0, 0); CP_COMMIT();

    for (int gs = 0; gs < NSLABS_TOTAL; gs++) {
        const int buf = gs & 1, s = gs & 1, nt = gs >> 1;
        if (gs + 1 < NSLABS_TOTAL) { issue_B(gs + 1, buf ^ 1); CP_COMMIT(); CP_WAIT1(); }
        else CP_WAIT0();
        __syncthreads();

        if (s == 0) {
#pragma unroll
            for (int mi = 0; mi < 2; mi++)
#pragma unroll
                for (int nf = 0; nf < 4; nf++)
#pragma unroll
                    for (int e = 0; e < 4; e++) acc[mi][nf][e] = 0;
        }

        // 4 k32 steps over this 128-elem K slab
#pragma unroll
        for (int kk = 0; kk < 4; kk++) {
            unsigned af[2][4], bf[2][4];
            const int aofs = s * 128 + kk * 32;
            const int bofs = kk * 32;
#pragma unroll
            for (int mi = 0; mi < 2; mi++) ldsm_x4(af[mi], aAddr[mi] + aofs);
#pragma unroll
            for (int np = 0; np < 2; np++) ldsm_x4(bf[np], bAddr[buf][np] + bofs);
#pragma unroll
            for (int mi = 0; mi < 2; mi++) {
#pragma unroll
                for (int np = 0; np < 2; np++) {
                    mma16832_s8(acc[mi][np * 2 + 0], af[mi], &bf[np][0]);
                    mma16832_s8(acc[mi][np * 2 + 1], af[mi], &bf[np][2]);
                }
            }
        }

        if (s == 1) {
            // update per-row depth-2 lists straight from fragments (no smem, no barrier)
            const int cb = c0 + nt * TN + wn * 32 + (lane & 3) * 2;
#pragma unroll
            for (int mi = 0; mi < 2; mi++) {
#pragma unroll
                for (int h = 0; h < 2; h++) {
                    const int L = mi * 2 + h;
#pragma unroll
                    for (int nf = 0; nf < 4; nf++) {
#pragma unroll
                        for (int e2 = 0; e2 < 2; e2++) {
                            int v = acc[mi][nf][h * 2 + e2];
                            if (v > lv1[L]) {
                                int col = cb + nf * 8 + e2;
                                if (v > lv0[L]) {
                                    lv1[L] = lv0[L]; li1[L] = li0[L];
                                    lv0[L] = v;      li0[L] = col;
                                } else {
                                    lv1[L] = v; li1[L] = col;
                                }
                            }
                        }
                    }
                }
            }
        }
    }

    // raw emission: per (thread,row) write 2 entries; 32 per (query,chunk)
    {
        const int slot = (wn * 4 + (lane & 3)) * 2;
#pragma unroll
        for (int mi = 0; mi < 2; mi++) {
#pragma unroll
            for (int h = 0; h < 2; h++) {
                const int L = mi * 2 + h;
                int qrow = q0 + wm * 32 + mi * 16 + (lane >> 2) + h * 8;
                size_t base = ((size_t)qrow * NCHUNKS + blockIdx.y) * PCHUNK + slot;
                g_pscore[base]     = (float)lv0[L];   // |acc| < 2^23 -> exact
                g_pidx[base]       = li0[L];
                g_pscore[base + 1] = (float)lv1[L];
                g_pidx[base + 1]   = li1[L];
            }
        }
    }
}

// ---- kernel 4: warp-per-query float4 sweep over 4096 entries -> 256 cand ----
__global__ __launch_bounds__(256) void prune_kernel() {
    const int wid = threadIdx.x >> 5, lane = threadIdx.x & 31;
    const int q = blockIdx.x * 8 + wid;
    const float4* ps4 = (const float4*)(g_pscore + (size_t)q * NCHUNKS * PCHUNK);
    const int4*   pi4 = (const int4*)(g_pidx + (size_t)q * NCHUNKS * PCHUNK);

    float ts[8]; int ti[8];
#pragma unroll
    for (int j = 0; j < 8; j++) { ts[j] = -INFINITY; ti[j] = 0x7fffffff; }
#pragma unroll 4
    for (int pass = 0; pass < 32; pass++) {
        int e4 = pass * 32 + lane;         // lane covers fixed 4-slot set across chunks
        float4 v = ps4[e4];
        int4   ii = pi4[e4];
        if (v.x > ts[7]) ins8(ts, ti, v.x, ii.x);
        if (v.y > ts[7]) ins8(ts, ti, v.y, ii.y);
        if (v.z > ts[7]) ins8(ts, ti, v.z, ii.z);
        if (v.w > ts[7]) ins8(ts, ti, v.w, ii.w);
    }
#pragma unroll
    for (int j = 0; j < 8; j++)
        g_cand[(size_t)q * NCAND + lane * 8 + j] = ti[j];
}

// ---- kernel 5: exact fp32 rescore of 256 candidates + final top-8 ----
__global__ __launch_bounds__(256) void rescore_kernel(const float* __restrict__ keys,
                                                      float* __restrict__ out_scores) {
    __shared__ float cs[NCAND];
    __shared__ int   ci[NCAND];
    int q = blockIdx.x;
    int wid = threadIdx.x >> 5, lane = threadIdx.x & 31;

    float qv[8];
    *(float4*)&qv[0] = *(const float4*)(g_qn + q * KDIM + lane * 8);
    *(float4*)&qv[4] = *(const float4*)(g_qn + q * KDIM + lane * 8 + 4);

    for (int c = wid; c < NCAND; c += 8) {
        int idx = g_cand[(size_t)q * NCAND + c];
        float kv[8];
        *(float4*)&kv[0] = *(const float4*)(keys + (size_t)idx * KDIM + lane * 8);
        *(float4*)&kv[4] = *(const float4*)(keys + (size_t)idx * KDIM + lane * 8 + 4);
        float ss = 0.f, dt = 0.f;
#pragma unroll
        for (int e = 0; e < 8; e++) { ss += kv[e] * kv[e]; dt += kv[e] * qv[e]; }
#pragma unroll
        for (int o = 16; o > 0; o >>= 1) {
            ss += __shfl_xor_sync(0xffffffffu, ss, o);
            dt += __shfl_xor_sync(0xffffffffu, dt, o);
        }
        if (lane == 0) {
            cs[c] = dt / fmaxf(sqrtf(ss), 1e-12f);
            ci[c] = idx;
        }
    }
    __syncthreads();
    if (threadIdx.x == 0) {
        float ts[TOPK]; int ti[TOPK];
#pragma unroll
        for (int j = 0; j < TOPK; j++) { ts[j] = -INFINITY; ti[j] = 0x7fffffff; }
        for (int c = 0; c < NCAND; c++) {
            float v = cs[c]; int id = ci[c];
            if (better(v, id, ts[TOPK - 1], ti[TOPK - 1])) {
                ts[TOPK - 1] = v; ti[TOPK - 1] = id;
#pragma unroll
                for (int j = TOPK - 1; j > 0; j--) {
                    if (better(ts[j], ti[j], ts[j - 1], ti[j - 1])) {
                        float tf = ts[j]; ts[j] = ts[j - 1]; ts[j - 1] = tf;
                        int   tt = ti[j]; ti[j] = ti[j - 1]; ti[j - 1] = tt;
                    }
                }
            }
        }
#pragma unroll
        for (int j = 0; j < TOPK; j++) {
            out_scores[q * TOPK + j] = ts[j];
            g_topidx[q * TOPK + j]   = ti[j];
        }
    }
}

// ---- kernel 6: gather docs ----
__global__ void gather_kernel(const float* __restrict__ vals, float* __restrict__ out_docs) {
    int b = blockIdx.x;
    int idx = g_topidx[b];
    const float4* src = (const float4*)(vals + (size_t)idx * DMODEL);
    float4* dst = (float4*)(out_docs + (size_t)b * DMODEL);
    dst[threadIdx.x] = src[threadIdx.x];
}

extern "C" void kernel_launch(void* const* d_in, const int* in_sizes, int n_in,
                              void* d_out, int out_size) {
    const float* query = (const float*)d_in[0];
    const float* keys  = (const float*)d_in[1];
    const float* vals  = (const float*)d_in[2];
    float* out        = (float*)d_out;
    float* out_docs   = out;
    float* out_scores = out + (size_t)B_Q * TOPK * DMODEL;

    qnorm_kernel<<<B_Q / 8, 256>>>(query);
    keysprep_kernel<<<NCORP / 8, 256>>>(keys);

    cudaFuncSetAttribute(score_kernel,
                         cudaFuncAttributeMaxDynamicSharedMemorySize, SMEM_TOTAL);
    score_kernel<<<dim3(QTILES, NCHUNKS), 512, SMEM_TOTAL>>>();

    prune_kernel<<<B_Q / 8, 256>>>();
    rescore_kernel<<<B_Q, 256>>>(keys, out_scores);
    gather_kernel<<<B_Q * TOPK, 256>>>(vals, out_docs);
}

// round 17
// speedup vs baseline: 1.3268x; 1.3268x over previous
#include <cuda_runtime.h>
#include <math.h>
#include <stdint.h>

#define B_Q    1024
#define NCORP  262144
#define KDIM   256
#define DMODEL 1024
#define TOPK   8
#define NCAND  256
#define PCHUNK 32                    // raw entries per (query, chunk)

#define TM      128
#define NCHUNKS 128
#define CHUNK   2048
#define NTILES  16                   // 128-col tiles per chunk (64 mma + 64 dp4a each)
#define QTILES  8
#define NSLABS_TOTAL (NTILES * 2)    // 32 x 128-elem K slabs

// byte pitches (odd 16B-unit counts -> conflict-free ldsm)
#define LDA_B  272      // A s8: 256B data + 16B pad
#define LDB_B  144      // B s8 slab: 128B data + 16B pad

#define SM_A     0
#define A_BYTES  (128 * LDA_B)              // 34816
#define SM_B     A_BYTES
#define SB_BYTES (128 * LDB_B)              // 18432 per buffer
#define SMEM_TOTAL (SM_B + 2 * SB_BYTES)    // 71680

#define QSCALE 256.0f

// ---- device-global scratch ----
__device__ unsigned char g_qs8[B_Q * KDIM];
__device__ float         g_qn[B_Q * KDIM];
__device__ unsigned char g_keysS8[(size_t)NCORP * KDIM];           // 64 MB
__device__ float         g_pscore[(size_t)B_Q * NCHUNKS * PCHUNK]; // 16 MB
__device__ int           g_pidx[(size_t)B_Q * NCHUNKS * PCHUNK];   // 16 MB
__device__ int           g_cand[B_Q * NCAND];                      // 1 MB
__device__ int           g_topidx[B_Q * TOPK];

__device__ __forceinline__ bool better(float s1, int i1, float s2, int i2) {
    return (s1 > s2) || (s1 == s2 && i1 < i2);
}
__device__ __forceinline__ uint32_t smem_u32(const void* p) {
    return (uint32_t)__cvta_generic_to_shared(p);
}
__device__ __forceinline__ void ldsm_x4(unsigned* r, unsigned addr) {
    asm volatile("ldmatrix.sync.aligned.m8n8.x4.shared.b16 {%0,%1,%2,%3}, [%4];\n"
        : "=r"(r[0]), "=r"(r[1]), "=r"(r[2]), "=r"(r[3]) : "r"(addr));
}
// int8 IMMA: m16n8k32 s8*s8 -> s32
__device__ __forceinline__ void mma16832_s8(int* d, const unsigned* a, const unsigned* b) {
    asm volatile(
        "mma.sync.aligned.m16n8k32.row.col.s32.s8.s8.s32 "
        "{%0,%1,%2,%3}, {%4,%5,%6,%7}, {%8,%9}, {%0,%1,%2,%3};\n"
        : "+r"(d[0]), "+r"(d[1]), "+r"(d[2]), "+r"(d[3])
        : "r"(a[0]), "r"(a[1]), "r"(a[2]), "r"(a[3]), "r"(b[0]), "r"(b[1]));
}
#define CP_ASYNC16(dst, src) \
    asm volatile("cp.async.cg.shared.global [%0], [%1], 16;" :: "r"(dst), "l"(src))
#define CP_COMMIT() asm volatile("cp.async.commit_group;" ::: "memory")
#define CP_WAIT1()  asm volatile("cp.async.wait_group 1;" ::: "memory")
#define CP_WAIT0()  asm volatile("cp.async.wait_group 0;" ::: "memory")

__device__ __forceinline__ void ins8(float ts[8], int ti[8], float v, int idx) {
    ts[7] = v; ti[7] = idx;
#pragma unroll
    for (int j = 7; j > 0; j--) {
        if (ts[j] > ts[j - 1]) {
            float tf = ts[j]; ts[j] = ts[j - 1]; ts[j - 1] = tf;
            int   tt = ti[j]; ti[j] = ti[j - 1]; ti[j - 1] = tt;
        }
    }
}

__device__ __forceinline__ signed char to_s8(float v) {
    return (signed char)__float2int_rn(fminf(fmaxf(v * QSCALE, -127.f), 127.f));
}

// ---- kernel 1: normalize queries -> fp32 + s8 ----
__global__ void qnorm_kernel(const float* __restrict__ q) {
    int row  = (blockIdx.x * blockDim.x + threadIdx.x) >> 5;
    int lane = threadIdx.x & 31;
    if (row >= B_Q) return;
    float x[8];
    *(float4*)&x[0] = *(const float4*)(q + row * KDIM + lane * 8);
    *(float4*)&x[4] = *(const float4*)(q + row * KDIM + lane * 8 + 4);
    float ss = 0.f;
#pragma unroll
    for (int e = 0; e < 8; e++) ss += x[e] * x[e];
#pragma unroll
    for (int o = 16; o > 0; o >>= 1) ss += __shfl_xor_sync(0xffffffffu, ss, o);
    float rinv = 1.0f / fmaxf(sqrtf(ss), 1e-12f);
    signed char ob[8];
#pragma unroll
    for (int e = 0; e < 8; e++) {
        float v = x[e] * rinv;
        g_qn[row * KDIM + lane * 8 + e] = v;
        ob[e] = to_s8(v);
    }
    *(uint2*)(g_qs8 + row * KDIM + lane * 8) = *(uint2*)ob;
}

// ---- kernel 2: normalize keys -> s8 row-major ----
__global__ void keysprep_kernel(const float* __restrict__ keys) {
    int row  = (blockIdx.x * blockDim.x + threadIdx.x) >> 5;
    int lane = threadIdx.x & 31;
    if (row >= NCORP) return;
    float x[8];
    *(float4*)&x[0] = *(const float4*)(keys + (size_t)row * KDIM + lane * 8);
    *(float4*)&x[4] = *(const float4*)(keys + (size_t)row * KDIM + lane * 8 + 4);
    float ss = 0.f;
#pragma unroll
    for (int e = 0; e < 8; e++) ss += x[e] * x[e];
#pragma unroll
    for (int o = 16; o > 0; o >>= 1) ss += __shfl_xor_sync(0xffffffffu, ss, o);
    float rinv = 1.0f / fmaxf(sqrtf(ss), 1e-12f);
    signed char ob[8];
#pragma unroll
    for (int e = 0; e < 8; e++) ob[e] = to_s8(x[e] * rinv);
    *(uint2*)(g_keysS8 + (size_t)row * KDIM + lane * 8) = *(uint2*)ob;
}

// ---- kernel 3: dual-pipe GEMM: warps 0-7 IMMA (cols 0-63/tile),
//                warps 8-15 DP4A (cols 64-127/tile); fragment-local top-2 ----
__global__ __launch_bounds__(512, 1) void score_kernel() {
    extern __shared__ char smem[];
    char* sA = smem + SM_A;
    char* sB = smem + SM_B;

    const int t = threadIdx.x, lane = t & 31, wid = t >> 5;
    const int q0 = blockIdx.x * TM;
    const int c0 = blockIdx.y * CHUNK;

    // A resident fill: 128 rows x 256B s8 (both pipes read it)
#pragma unroll
    for (int i = 0; i < 4; i++) {
        int u = i * 512 + t; int row = u >> 4, seg = u & 15;
        uint4 v = *(const uint4*)(g_qs8 + (size_t)(q0 + row) * KDIM + seg * 16);
        *(uint4*)(sA + row * LDA_B + seg * 16) = v;
    }

    // ---- mma-side addressing (warps 0..7): warp tile 32 rows x 32 cols ----
    const int wm = wid >> 1, wn = wid & 1;          // 4x2 grid over 128x64 mma part
    unsigned aAddr[2];
    {
        int r = lane & 15, c8 = lane >> 4;
#pragma unroll
        for (int mi = 0; mi < 2; mi++)
            aAddr[mi] = smem_u32(sA + (wm * 32 + mi * 16 + r) * LDA_B + c8 * 16);
    }
    unsigned bAddr[2][2];
    {
        int bn = (lane & 7) + ((lane >> 4) << 3);
        int bk = ((lane >> 3) & 1) * 16;
#pragma unroll
        for (int buf = 0; buf < 2; buf++)
#pragma unroll
            for (int np = 0; np < 2; np++)
                bAddr[buf][np] = smem_u32(sB + buf * SB_BYTES +
                                          (wn * 32 + np * 16 + bn) * LDB_B + bk);
    }

    // ---- dp4a-side addressing (warps 8..15) ----
    const int t2 = t - 256;                 // 0..255 for dp4a threads
    const int cb = t2 & 7, qb = t2 >> 3;    // 8 col-slots, 32 q-blocks of 4

    // 4 depth-2 lists (shared register set: mma rows / dp4a queries)
    int lv0[4], lv1[4], li0[4], li1[4];
#pragma unroll
    for (int L = 0; L < 4; L++) {
        lv0[L] = INT32_MIN; lv1[L] = INT32_MIN;
        li0[L] = 0x7fffffff; li1[L] = 0x7fffffff;
    }

    // cp.async: slab gs (tile gs>>1, K-half gs&1) -> buffer buf (16KB)
    auto issue_B = [&](int gs, int buf) {
        const int nt = gs >> 1, s = gs & 1;
        const unsigned char* src = g_keysS8 + (size_t)(c0 + nt * 128) * KDIM + s * 128;
        char* dst = sB + buf * SB_BYTES;
#pragma unroll
        for (int i = 0; i < 2; i++) {
            int u = i * 512 + t; int row = u >> 3, seg = u & 7;
            CP_ASYNC16(smem_u32(dst + row * LDB_B + seg * 16),
                       (const void*)(src + (size_t)row * KDIM + seg * 16));
        }
    };

    int acc[2][4][4];       // mma accumulators (warps 0..7)
    int dacc[4][8];         // dp4a accumulators (warps 8..15): 4q x 8c

    issue_B(0, 0); CP_COMMIT();

    for (int gs = 0; gs < NSLABS_TOTAL; gs++) {
        const int buf = gs & 1, s = gs & 1, nt = gs >> 1;
        if (gs + 1 < NSLABS_TOTAL) { issue_B(gs + 1, buf ^ 1); CP_COMMIT(); CP_WAIT1(); }
        else CP_WAIT0();
        __syncthreads();

        if (wid < 8) {
            // ================= IMMA pipe: cols [0,64) of tile =================
            if (s == 0) {
#pragma unroll
                for (int mi = 0; mi < 2; mi++)
#pragma unroll
                    for (int nf = 0; nf < 4; nf++)
#pragma unroll
                        for (int e = 0; e < 4; e++) acc[mi][nf][e] = 0;
            }
#pragma unroll
            for (int kk = 0; kk < 4; kk++) {
                unsigned af[2][4], bf[2][4];
                const int aofs = s * 128 + kk * 32;
                const int bofs = kk * 32;
#pragma unroll
                for (int mi = 0; mi < 2; mi++) ldsm_x4(af[mi], aAddr[mi] + aofs);
#pragma unroll
                for (int np = 0; np < 2; np++) ldsm_x4(bf[np], bAddr[buf][np] + bofs);
#pragma unroll
                for (int mi = 0; mi < 2; mi++) {
#pragma unroll
                    for (int np = 0; np < 2; np++) {
                        mma16832_s8(acc[mi][np * 2 + 0], af[mi], &bf[np][0]);
                        mma16832_s8(acc[mi][np * 2 + 1], af[mi], &bf[np][2]);
                    }
                }
            }
            if (s == 1) {
                const int cbB = c0 + nt * 128 + wn * 32 + (lane & 3) * 2;
#pragma unroll
                for (int mi = 0; mi < 2; mi++) {
#pragma unroll
                    for (int h = 0; h < 2; h++) {
                        const int L = mi * 2 + h;
#pragma unroll
                        for (int nf = 0; nf < 4; nf++) {
#pragma unroll
                            for (int e2 = 0; e2 < 2; e2++) {
                                int v = acc[mi][nf][h * 2 + e2];
                                if (v > lv1[L]) {
                                    int col = cbB + nf * 8 + e2;
                                    if (v > lv0[L]) {
                                        lv1[L] = lv0[L]; li1[L] = li0[L];
                                        lv0[L] = v;      li0[L] = col;
                                    } else {
                                        lv1[L] = v; li1[L] = col;
                                    }
                                }
                            }
                        }
                    }
                }
            }
        } else {
            // ================= DP4A pipe: cols [64,128) of tile =================
            if (s == 0) {
#pragma unroll
                for (int j = 0; j < 4; j++)
#pragma unroll
                    for (int c = 0; c < 8; c++) dacc[j][c] = 0;
            }
            const char* bBase = sB + buf * SB_BYTES;
            const int kofs = s * 128;
#pragma unroll
            for (int k16 = 0; k16 < 8; k16++) {
                int4 a[4];
#pragma unroll
                for (int j = 0; j < 4; j++)
                    a[j] = *(const int4*)(sA + (qb * 4 + j) * LDA_B + kofs + k16 * 16);
#pragma unroll
                for (int c = 0; c < 8; c++) {
                    int4 b = *(const int4*)(bBase + (64 + cb + 8 * c) * LDB_B + k16 * 16);
#pragma unroll
                    for (int j = 0; j < 4; j++) {
                        dacc[j][c] = __dp4a(a[j].x, b.x, dacc[j][c]);
                        dacc[j][c] = __dp4a(a[j].y, b.y, dacc[j][c]);
                        dacc[j][c] = __dp4a(a[j].z, b.z, dacc[j][c]);
                        dacc[j][c] = __dp4a(a[j].w, b.w, dacc[j][c]);
                    }
                }
            }
            if (s == 1) {
                const int cbD = c0 + nt * 128 + 64 + cb;
#pragma unroll
                for (int j = 0; j < 4; j++) {
#pragma unroll
                    for (int c = 0; c < 8; c++) {
                        int v = dacc[j][c];
                        if (v > lv1[j]) {
                            int col = cbD + 8 * c;
                            if (v > lv0[j]) {
                                lv1[j] = lv0[j]; li1[j] = li0[j];
                                lv0[j] = v;      li0[j] = col;
                            } else {
                                lv1[j] = v; li1[j] = col;
                            }
                        }
                    }
                }
            }
        }

        // REQUIRED: consumers of this slab's buffer must finish before the
        // next iteration's cp.async prefetch overwrites it (R16 raced here).
        __syncthreads();
    }

    // raw emission: 32 entries per (query, chunk): mma slots 0-15, dp4a 16-31
    if (wid < 8) {
        const int slot = (wn * 4 + (lane & 3)) * 2;
#pragma unroll
        for (int mi = 0; mi < 2; mi++) {
#pragma unroll
            for (int h = 0; h < 2; h++) {
                const int L = mi * 2 + h;
                int qrow = q0 + wm * 32 + mi * 16 + (lane >> 2) + h * 8;
                size_t base = ((size_t)qrow * NCHUNKS + blockIdx.y) * PCHUNK + slot;
                g_pscore[base]     = (float)lv0[L];   // |acc| < 2^23 -> exact
                g_pidx[base]       = li0[L];
                g_pscore[base + 1] = (float)lv1[L];
                g_pidx[base + 1]   = li1[L];
            }
        }
    } else {
        const int slot = 16 + cb * 2;
#pragma unroll
        for (int j = 0; j < 4; j++) {
            int qrow = q0 + qb * 4 + j;
            size_t base = ((size_t)qrow * NCHUNKS + blockIdx.y) * PCHUNK + slot;
            g_pscore[base]     = (float)lv0[j];
            g_pidx[base]       = li0[j];
            g_pscore[base + 1] = (float)lv1[j];
            g_pidx[base + 1]   = li1[j];
        }
    }
}

// ---- kernel 4: warp-per-query float4 sweep over 4096 entries -> 256 cand ----
__global__ __launch_bounds__(256) void prune_kernel() {
    const int wid = threadIdx.x >> 5, lane = threadIdx.x & 31;
    const int q = blockIdx.x * 8 + wid;
    const float4* ps4 = (const float4*)(g_pscore + (size_t)q * NCHUNKS * PCHUNK);
    const int4*   pi4 = (const int4*)(g_pidx + (size_t)q * NCHUNKS * PCHUNK);

    float ts[8]; int ti[8];
#pragma unroll
    for (int j = 0; j < 8; j++) { ts[j] = -INFINITY; ti[j] = 0x7fffffff; }
#pragma unroll 4
    for (int pass = 0; pass < 32; pass++) {
        int e4 = pass * 32 + lane;         // lane covers fixed 4-slot set across chunks
        float4 v = ps4[e4];
        int4   ii = pi4[e4];
        if (v.x > ts[7]) ins8(ts, ti, v.x, ii.x);
        if (v.y > ts[7]) ins8(ts, ti, v.y, ii.y);
        if (v.z > ts[7]) ins8(ts, ti, v.z, ii.z);
        if (v.w > ts[7]) ins8(ts, ti, v.w, ii.w);
    }
#pragma unroll
    for (int j = 0; j < 8; j++)
        g_cand[(size_t)q * NCAND + lane * 8 + j] = ti[j];
}

// ---- kernel 5: exact fp32 rescore of 256 candidates + final top-8 ----
__global__ __launch_bounds__(256) void rescore_kernel(const float* __restrict__ keys,
                                                      float* __restrict__ out_scores) {
    __shared__ float cs[NCAND];
    __shared__ int   ci[NCAND];
    int q = blockIdx.x;
    int wid = threadIdx.x >> 5, lane = threadIdx.x & 31;

    float qv[8];
    *(float4*)&qv[0] = *(const float4*)(g_qn + q * KDIM + lane * 8);
    *(float4*)&qv[4] = *(const float4*)(g_qn + q * KDIM + lane * 8 + 4);

    for (int c = wid; c < NCAND; c += 8) {
        int idx = g_cand[(size_t)q * NCAND + c];
        float kv[8];
        *(float4*)&kv[0] = *(const float4*)(keys + (size_t)idx * KDIM + lane * 8);
        *(float4*)&kv[4] = *(const float4*)(keys + (size_t)idx * KDIM + lane * 8 + 4);
        float ss = 0.f, dt = 0.f;
#pragma unroll
        for (int e = 0; e < 8; e++) { ss += kv[e] * kv[e]; dt += kv[e] * qv[e]; }
#pragma unroll
        for (int o = 16; o > 0; o >>= 1) {
            ss += __shfl_xor_sync(0xffffffffu, ss, o);
            dt += __shfl_xor_sync(0xffffffffu, dt, o);
        }
        if (lane == 0) {
            cs[c] = dt / fmaxf(sqrtf(ss), 1e-12f);
            ci[c] = idx;
        }
    }
    __syncthreads();
    if (threadIdx.x == 0) {
        float ts[TOPK]; int ti[TOPK];
#pragma unroll
        for (int j = 0; j < TOPK; j++) { ts[j] = -INFINITY; ti[j] = 0x7fffffff; }
        for (int c = 0; c < NCAND; c++) {
            float v = cs[c]; int id = ci[c];
            if (better(v, id, ts[TOPK - 1], ti[TOPK - 1])) {
                ts[TOPK - 1] = v; ti[TOPK - 1] = id;
#pragma unroll
                for (int j = TOPK - 1; j > 0; j--) {
                    if (better(ts[j], ti[j], ts[j - 1], ti[j - 1])) {
                        float tf = ts[j]; ts[j] = ts[j - 1]; ts[j - 1] = tf;
                        int   tt = ti[j]; ti[j] = ti[j - 1]; ti[j - 1] = tt;
                    }
                }
            }
        }
#pragma unroll
        for (int j = 0; j < TOPK; j++) {
            out_scores[q * TOPK + j] = ts[j];
            g_topidx[q * TOPK + j]   = ti[j];
        }
    }
}

// ---- kernel 6: gather docs ----
__global__ void gather_kernel(const float* __restrict__ vals, float* __restrict__ out_docs) {
    int b = blockIdx.x;
    int idx = g_topidx[b];
    const float4* src = (const float4*)(vals + (size_t)idx * DMODEL);
    float4* dst = (float4*)(out_docs + (size_t)b * DMODEL);
    dst[threadIdx.x] = src[threadIdx.x];
}

extern "C" void kernel_launch(void* const* d_in, const int* in_sizes, int n_in,
                              void* d_out, int out_size) {
    const float* query = (const float*)d_in[0];
    const float* keys  = (const float*)d_in[1];
    const float* vals  = (const float*)d_in[2];
    float* out        = (float*)d_out;
    float* out_docs   = out;
    float* out_scores = out + (size_t)B_Q * TOPK * DMODEL;

    qnorm_kernel<<<B_Q / 8, 256>>>(query);
    keysprep_kernel<<<NCORP / 8, 256>>>(keys);

    cudaFuncSetAttribute(score_kernel,
                         cudaFuncAttributeMaxDynamicSharedMemorySize, SMEM_TOTAL);
    score_kernel<<<dim3(QTILES, NCHUNKS), 512, SMEM_TOTAL>>>();

    prune_kernel<<<B_Q / 8, 256>>>();
    rescore_kernel<<<B_Q, 256>>>(keys, out_scores);
    gather_kernel<<<B_Q * TOPK, 256>>>(vals, out_docs);
}